// round 2
// baseline (speedup 1.0000x reference)
#include <cuda_runtime.h>

#define BB 1024
#define TT 512
#define H1C 80
#define G1 320
#define H2C 100
#define G2 400

// Scratch (static device arrays: allocation-free per harness rules)
__device__ float g_h1[(size_t)TT * BB * H1C];      // relu(h1): 168 MB, layout [t][b][u]
__device__ float g_xg2[(size_t)TT * BB * G2];      // layer-2 gate pre-acts: 839 MB, [t][b][g]
__device__ float g_h2last[BB * H2C];               // relu(h2) at t=T-1

__device__ __forceinline__ float2 ffma2(float2 d, float2 a, float2 b) {
    unsigned long long dd = *reinterpret_cast<unsigned long long*>(&d);
    unsigned long long aa = *reinterpret_cast<unsigned long long*>(&a);
    unsigned long long bb = *reinterpret_cast<unsigned long long*>(&b);
    asm("fma.rn.f32x2 %0, %1, %2, %0;" : "+l"(dd) : "l"(aa), "l"(bb));
    return *reinterpret_cast<float2*>(&dd);
}

__device__ __forceinline__ float sigm(float x) { return 1.0f / (1.0f + __expf(-x)); }
__device__ __forceinline__ float tanh_(float x) { return 2.0f / (1.0f + __expf(-2.0f * x)) - 1.0f; }

// ---------------------------------------------------------------------------
// Kernel 1: layer-1 LSTM. 128 CTAs x 8 batches, persistent over T.
// Exact-balance matvec: 256 threads = 32 j-groups (10 j) x 8 k-groups (10 k).
// Per-thread: 5 j-pairs x 8 batches, FFMA2. All 8 warps equal -> SMSPs balanced.
// h stored duplicated as float2 (h,h) so matvec uses 1 broadcast LDS.64/(k,b).
// c-state lives in registers (fixed item->thread map). 2 barriers/step.
// SMEM: Wt[80][320] + wx[320] + bs[320] + hd[640]f2 + gs[8][8][320] + xall[8][512]
// ---------------------------------------------------------------------------
__global__ void __launch_bounds__(256, 1)
lstm1_kernel(const float* __restrict__ x, const float* __restrict__ W_ih1,
             const float* __restrict__ W_hh1, const float* __restrict__ b_ih1,
             const float* __restrict__ b_hh1) {
    extern __shared__ float sm[];
    float*  Wt   = sm;                          // 25600
    float*  wx   = Wt + 25600;                  // 320
    float*  bs   = wx + 320;                    // 320
    float2* hd   = (float2*)(bs + 320);         // 640 float2 (1280 floats) [u*8+b]
    float*  gs   = (float*)(hd + 640);          // 20480  [kg][b][320]
    float*  xall = gs + 20480;                  // 4096   [b][t]

    const int tid = threadIdx.x;
    const int b0  = blockIdx.x * 8;

    for (int i = tid; i < G1 * H1C; i += 256) {
        int j = i / H1C, k = i - j * H1C;
        Wt[k * G1 + j] = W_hh1[i];
    }
    for (int i = tid; i < G1; i += 256) { wx[i] = W_ih1[i]; bs[i] = b_ih1[i] + b_hh1[i]; }
    for (int i = tid; i < 640; i += 256) hd[i] = make_float2(0.f, 0.f);
    for (int i = tid; i < 8 * TT; i += 256) {
        int b = i >> 9, t = i & 511;
        xall[i] = x[(size_t)(b0 + b) * TT + t];
    }
    __syncthreads();

    const int kg = tid >> 5;          // 8 k-groups of 10
    const int jg = tid & 31;          // 32 j-groups of 10
    const int j0 = jg * 10;
    const int k0 = kg * 10;

    // activation items: 640 (b,u) pairs -> threads get 2 or 3 (tid<128 -> 3)
    const int nit = (tid < 128) ? 3 : 2;
    int itb[3], itu[3];
    float cst[3] = {0.f, 0.f, 0.f};
#pragma unroll
    for (int r = 0; r < 3; ++r) {
        int it = tid + 256 * r;
        itb[r] = it / 80;
        itu[r] = it - itb[r] * 80;
    }

    for (int t = 0; t < TT; ++t) {
        // ---- matvec: partial gates for k in [k0, k0+10) ----
        float2 a[5][8];
#pragma unroll
        for (int jp = 0; jp < 5; ++jp)
#pragma unroll
            for (int b = 0; b < 8; ++b) a[jp][b] = make_float2(0.f, 0.f);

        const float*  wp = Wt + k0 * G1 + j0;
        const float2* hp = hd + k0 * 8;
#pragma unroll 5
        for (int k = 0; k < 10; ++k) {
            float2 w0 = *(const float2*)(wp + 0);
            float2 w1 = *(const float2*)(wp + 2);
            float2 w2 = *(const float2*)(wp + 4);
            float2 w3 = *(const float2*)(wp + 6);
            float2 w4 = *(const float2*)(wp + 8);
            wp += G1;
#pragma unroll
            for (int b = 0; b < 8; ++b) {
                float2 hb = hp[b];     // broadcast (h,h)
                a[0][b] = ffma2(a[0][b], w0, hb);
                a[1][b] = ffma2(a[1][b], w1, hb);
                a[2][b] = ffma2(a[2][b], w2, hb);
                a[3][b] = ffma2(a[3][b], w3, hb);
                a[4][b] = ffma2(a[4][b], w4, hb);
            }
            hp += 8;
        }
        {
            float* gp0 = gs + kg * 2560 + j0;
#pragma unroll
            for (int b = 0; b < 8; ++b)
#pragma unroll
                for (int jp = 0; jp < 5; ++jp)
                    *(float2*)(gp0 + b * G1 + jp * 2) = a[jp][b];
        }
        __syncthreads();

        // ---- activation: sum 8 partials + x*wx + bias ----
#pragma unroll
        for (int r = 0; r < 3; ++r) {
            if (r < nit) {
                const int b = itb[r], u = itu[r];
                const float xv = xall[b * TT + t];
                const float* gb = gs + b * G1;
                float s0 = xv * wx[u]       + bs[u];
                float s1 = xv * wx[80 + u]  + bs[80 + u];
                float s2 = xv * wx[160 + u] + bs[160 + u];
                float s3 = xv * wx[240 + u] + bs[240 + u];
#pragma unroll
                for (int q = 0; q < 8; ++q) {
                    const float* gq = gb + q * 2560;
                    s0 += gq[u];
                    s1 += gq[80 + u];
                    s2 += gq[160 + u];
                    s3 += gq[240 + u];
                }
                float ig = sigm(s0), fg = sigm(s1), gg = tanh_(s2), og = sigm(s3);
                float c = fg * cst[r] + ig * gg;
                cst[r] = c;
                float h = og * tanh_(c);
                hd[u * 8 + b] = make_float2(h, h);
                g_h1[(size_t)t * (BB * H1C) + (size_t)(b0 + b) * H1C + u] = fmaxf(h, 0.0f);
            }
        }
        __syncthreads();
    }
}

// ---------------------------------------------------------------------------
// Kernel 2: xg2 = relu(h1) @ W_ih2^T + (b_ih2 + b_hh2).  Persistent, 148 blocks.
// (unchanged this round; candidate for tf32 tensor cores next)
// ---------------------------------------------------------------------------
__global__ void __launch_bounds__(256, 1)
xg2_gemm_kernel(const float* __restrict__ W_ih2, const float* __restrict__ b_ih2,
                const float* __restrict__ b_hh2) {
    extern __shared__ float sm[];
    float* Wt   = sm;            // 80*400 = 32000 (transposed W_ih2)
    float* bias = Wt + 32000;    // 400
    float* As   = bias + 400;    // 32*80 = 2560

    const int tid = threadIdx.x;
    for (int i = tid; i < G2 * H1C; i += 256) {
        int jj = i / H1C, k = i - jj * H1C;
        Wt[k * G2 + jj] = W_ih2[i];
    }
    for (int i = tid; i < G2; i += 256) bias[i] = b_ih2[i] + b_hh2[i];

    const int  rg  = tid / 50;
    const int  cg  = tid - rg * 50;
    const bool act = tid < 200;
    const int  NT  = (TT * BB) / 32;

    for (int tile = blockIdx.x; tile < NT; tile += gridDim.x) {
        size_t r0 = (size_t)tile * 32;
        __syncthreads();
        for (int i = tid; i < 32 * H1C; i += 256) As[i] = g_h1[r0 * H1C + i];
        __syncthreads();
        if (act) {
            float2 acc[8][4];
#pragma unroll
            for (int i = 0; i < 8; ++i)
#pragma unroll
                for (int p = 0; p < 4; ++p) acc[i][p] = make_float2(0.f, 0.f);
            const float* ap = As + rg * 8 * H1C;
            const float* wp = Wt + cg * 8;
#pragma unroll 2
            for (int k = 0; k < H1C; ++k) {
                float2 w0 = *(const float2*)(wp + k * G2);
                float2 w1 = *(const float2*)(wp + k * G2 + 2);
                float2 w2 = *(const float2*)(wp + k * G2 + 4);
                float2 w3 = *(const float2*)(wp + k * G2 + 6);
#pragma unroll
                for (int i = 0; i < 8; ++i) {
                    float aval = ap[i * H1C + k];
                    float2 ad = make_float2(aval, aval);
                    acc[i][0] = ffma2(acc[i][0], w0, ad);
                    acc[i][1] = ffma2(acc[i][1], w1, ad);
                    acc[i][2] = ffma2(acc[i][2], w2, ad);
                    acc[i][3] = ffma2(acc[i][3], w3, ad);
                }
            }
            const int c = cg * 8;
#pragma unroll
            for (int i = 0; i < 8; ++i) {
                size_t row = r0 + (size_t)rg * 8 + i;
                float* op = g_xg2 + row * G2 + c;
#pragma unroll
                for (int p = 0; p < 4; ++p) {
                    float2 v = acc[i][p];
                    v.x += bias[c + 2 * p];
                    v.y += bias[c + 2 * p + 1];
                    *(float2*)(op + 2 * p) = v;
                }
            }
        }
    }
}

// ---------------------------------------------------------------------------
// Kernel 3: layer-2 LSTM. 128 CTAs x 8 batches, persistent over T.
// Matvec: 250 active threads = 50 j-groups (8 j, LDS.128 aligned) x 5 k-groups
// (20 k). Per-thread 4 j-pairs x 8 batches. xg prefetched via LDG at step top.
// SMEM: Wt[100][400] (160KB) + hd[800]f2 + gs[5][8][400]  = 230400 B
// ---------------------------------------------------------------------------
__global__ void __launch_bounds__(256, 1)
lstm2_kernel(const float* __restrict__ W_hh2) {
    extern __shared__ float sm[];
    float*  Wt = sm;                      // 40000
    float2* hd = (float2*)(Wt + 40000);   // 800 float2 (1600 floats) [u*8+b]
    float*  gs = (float*)(hd + 800);      // 16000  [kg][b][400]

    const int tid = threadIdx.x;
    const int b0  = blockIdx.x * 8;

    for (int i = tid; i < G2 * H2C; i += 256) {
        int jj = i / H2C, k = i - jj * H2C;
        Wt[k * G2 + jj] = W_hh2[i];
    }
    for (int i = tid; i < 800; i += 256) hd[i] = make_float2(0.f, 0.f);
    __syncthreads();

    const bool act = tid < 250;
    const int  kg  = tid / 50;            // 5 k-groups of 20 (kg=5 masked off)
    const int  jg  = tid - kg * 50;       // 50 j-groups of 8
    const int  j0  = jg * 8;
    const int  k0  = kg * 20;

    // activation items: 800 (b,u) pairs -> 3 each, tid<32 gets a 4th
    const int nit = (tid < 32) ? 4 : 3;
    int itb[4], itu[4];
    float cst[4] = {0.f, 0.f, 0.f, 0.f};
#pragma unroll
    for (int r = 0; r < 4; ++r) {
        int it = tid + 256 * r;
        itb[r] = it / 100;
        itu[r] = it - itb[r] * 100;
    }

    for (int t = 0; t < TT; ++t) {
        // ---- prefetch xg for this thread's activation items (hidden by k-loop) ----
        float xv[4][4];
#pragma unroll
        for (int r = 0; r < 4; ++r) {
            if (r < nit) {
                const float* xp = g_xg2 + (size_t)t * (BB * G2)
                                        + (size_t)(b0 + itb[r]) * G2 + itu[r];
                xv[r][0] = xp[0];
                xv[r][1] = xp[100];
                xv[r][2] = xp[200];
                xv[r][3] = xp[300];
            }
        }

        // ---- matvec: partial gates for k in [k0, k0+20) ----
        if (act) {
            float2 a[4][8];
#pragma unroll
            for (int jp = 0; jp < 4; ++jp)
#pragma unroll
                for (int b = 0; b < 8; ++b) a[jp][b] = make_float2(0.f, 0.f);

            const float*  wp = Wt + k0 * G2 + j0;
            const float2* hp = hd + k0 * 8;
#pragma unroll 5
            for (int k = 0; k < 20; ++k) {
                float4 wA = *(const float4*)(wp);
                float4 wB = *(const float4*)(wp + 4);
                wp += G2;
                float2 w0 = make_float2(wA.x, wA.y);
                float2 w1 = make_float2(wA.z, wA.w);
                float2 w2 = make_float2(wB.x, wB.y);
                float2 w3 = make_float2(wB.z, wB.w);
#pragma unroll
                for (int b = 0; b < 8; ++b) {
                    float2 hb = hp[b];   // broadcast (h,h)
                    a[0][b] = ffma2(a[0][b], w0, hb);
                    a[1][b] = ffma2(a[1][b], w1, hb);
                    a[2][b] = ffma2(a[2][b], w2, hb);
                    a[3][b] = ffma2(a[3][b], w3, hb);
                }
                hp += 8;
            }
            float* gp0 = gs + kg * 3200 + j0;
#pragma unroll
            for (int b = 0; b < 8; ++b)
#pragma unroll
                for (int jp = 0; jp < 4; ++jp)
                    *(float2*)(gp0 + b * G2 + jp * 2) = a[jp][b];
        }
        __syncthreads();

        // ---- activation: sum 5 partials + xg ----
#pragma unroll
        for (int r = 0; r < 4; ++r) {
            if (r < nit) {
                const int b = itb[r], u = itu[r];
                const float* gb = gs + b * G2;
                float s0 = xv[r][0], s1 = xv[r][1], s2 = xv[r][2], s3 = xv[r][3];
#pragma unroll
                for (int q = 0; q < 5; ++q) {
                    const float* gq = gb + q * 3200;
                    s0 += gq[u];
                    s1 += gq[100 + u];
                    s2 += gq[200 + u];
                    s3 += gq[300 + u];
                }
                float ig = sigm(s0), fg = sigm(s1), gg = tanh_(s2), og = sigm(s3);
                float c = fg * cst[r] + ig * gg;
                cst[r] = c;
                float h = og * tanh_(c);
                hd[u * 8 + b] = make_float2(h, h);
                if (t == TT - 1) g_h2last[(b0 + b) * H2C + u] = fmaxf(h, 0.0f);
            }
        }
        __syncthreads();
    }
}

// ---------------------------------------------------------------------------
// Kernel 4: final MLP head.
// ---------------------------------------------------------------------------
__global__ void fc_kernel(const float* __restrict__ W_l1, const float* __restrict__ b_l1,
                          const float* __restrict__ W_l2, const float* __restrict__ b_l2,
                          float* __restrict__ out) {
    __shared__ float wl1[10 * 100];
    __shared__ float bl1[10], wl2[10], bl2s;
    const int tid = threadIdx.x;
    for (int i = tid; i < 1000; i += 256) wl1[i] = W_l1[i];
    if (tid < 10) { bl1[tid] = b_l1[tid]; wl2[tid] = W_l2[tid]; }
    if (tid == 0) bl2s = b_l2[0];
    __syncthreads();

    const int b = blockIdx.x * 256 + tid;
    float acc[10];
#pragma unroll
    for (int jj = 0; jj < 10; ++jj) acc[jj] = bl1[jj];
    const float* hp = g_h2last + b * H2C;
    for (int k = 0; k < H2C; ++k) {
        float hk = hp[k];
#pragma unroll
        for (int jj = 0; jj < 10; ++jj) acc[jj] = fmaf(wl1[jj * 100 + k], hk, acc[jj]);
    }
    float o = bl2s;
#pragma unroll
    for (int jj = 0; jj < 10; ++jj) o += wl2[jj] * fmaxf(acc[jj], 0.0f);
    out[b] = o;
}

// ---------------------------------------------------------------------------
extern "C" void kernel_launch(void* const* d_in, const int* in_sizes, int n_in,
                              void* d_out, int out_size) {
    const float* x     = (const float*)d_in[0];
    const float* W_ih1 = (const float*)d_in[1];
    const float* W_hh1 = (const float*)d_in[2];
    const float* b_ih1 = (const float*)d_in[3];
    const float* b_hh1 = (const float*)d_in[4];
    const float* W_ih2 = (const float*)d_in[5];
    const float* W_hh2 = (const float*)d_in[6];
    const float* b_ih2 = (const float*)d_in[7];
    const float* b_hh2 = (const float*)d_in[8];
    const float* W_l1  = (const float*)d_in[9];
    const float* b_l1  = (const float*)d_in[10];
    const float* W_l2  = (const float*)d_in[11];
    const float* b_l2  = (const float*)d_in[12];

    const size_t smA = (size_t)(25600 + 320 + 320 + 1280 + 20480 + 4096) * 4; // 208384 B
    const size_t smG = (size_t)(32000 + 400 + 2560) * 4;                      // 139840 B
    const size_t smB = (size_t)(40000 + 1600 + 16000) * 4;                    // 230400 B

    cudaFuncSetAttribute(lstm1_kernel,    cudaFuncAttributeMaxDynamicSharedMemorySize, (int)smA);
    cudaFuncSetAttribute(xg2_gemm_kernel, cudaFuncAttributeMaxDynamicSharedMemorySize, (int)smG);
    cudaFuncSetAttribute(lstm2_kernel,    cudaFuncAttributeMaxDynamicSharedMemorySize, (int)smB);

    lstm1_kernel<<<128, 256, smA>>>(x, W_ih1, W_hh1, b_ih1, b_hh1);
    xg2_gemm_kernel<<<148, 256, smG>>>(W_ih2, b_ih2, b_hh2);
    lstm2_kernel<<<128, 256, smB>>>(W_hh2);
    fc_kernel<<<4, 256>>>(W_l1, b_l1, W_l2, b_l2, (float*)d_out);
}